// round 11
// baseline (speedup 1.0000x reference)
#include <cuda_runtime.h>
#include <math.h>

// Problem constants
#define NB        128      // persistent blocks (<= 148 SMs, all resident)
#define NT        512      // 16 warps = 16 warp-private k-groups
#define T_STEPS   512
#define BATCH     32
#define IN_SZ     512
#define OUT_SZ    512
#define LHID      512
#define NG        16       // k-groups (one warp each)
#define KPG       96       // K per group (1536/16)
#define KC        16       // k per chunk per group
#define NCH       6        // chunks (96/16)
#define PADK      20       // row stride 80B (quad stride 5 mod 8 -> conflict-free x loads)
#define SLICE     (32 * PADK)                  // 640 floats: per-warp slice
#define BUFSZ     (NG * SLICE)                 // 10240 floats per buffer
#define HN_BASE   (BATCH * T_STEPS * OUT_SZ)   // 8,388,608

// Persistent state (device globals; no allocation allowed)
__device__ float g_hbuf[2][2][2][BATCH][LHID];  // [parity][layer][dir][b][u]
__device__ float g_c[2][2][BATCH][LHID];        // [layer][dir][b][u]
__device__ float g_prev[BATCH][OUT_SZ];
__device__ unsigned int g_count = 0;
__device__ volatile unsigned int g_gen = 0;

__device__ __forceinline__ void grid_sync() {
    __threadfence();
    __syncthreads();
    if (threadIdx.x == 0) {
        unsigned gen = g_gen;
        if (atomicAdd(&g_count, 1u) == NB - 1) {
            g_count = 0;
            __threadfence();
            g_gen = gen + 1;
        } else {
            while (g_gen == gen) { }
        }
        __threadfence();
    }
    __syncthreads();
}

__device__ __forceinline__ float sigm(float x) { return 1.0f / (1.0f + expf(-x)); }

// cp.async (L2-only .cg path: coherent with other SMs' writes, no L1 staleness)
__device__ __forceinline__ void cp_async16(void* smem_dst, const void* gsrc) {
    unsigned saddr = (unsigned)__cvta_generic_to_shared(smem_dst);
    asm volatile("cp.async.cg.shared.global [%0], [%1], 16;\n" :: "r"(saddr), "l"(gsrc));
}
__device__ __forceinline__ void cp_commit() {
    asm volatile("cp.async.commit_group;\n");
}
template <int N> __device__ __forceinline__ void cp_wait() {
    asm volatile("cp.async.wait_group %0;\n" :: "n"(N));
}

// smem: w-buf0 [0..10240) | w-buf1 [10240..20480) | x-buf0 [20480..30720) | x-buf1 [30720..40960)
// overlays: red (16896 floats) -> [20480..37376)  (x-buf region)
//           FC: hs [0..32896) | wfc [32896..36992) | fcred [36992..37504)
// NOTE: wfc/fcred overlap red's tail -> any cp.async into wfc_s must be issued
// only after a block barrier that retires all red reads (the R10 bug).
#define SMEM_FLOATS (4 * BUFSZ)   // 40960
#define SMEM_BYTES  (SMEM_FLOATS * 4)

__global__ void __launch_bounds__(NT, 1)
ae_kernel(const float* __restrict__ x_in,
          const float* __restrict__ W_ih, const float* __restrict__ W_hh,
          const float* __restrict__ b_ih, const float* __restrict__ b_hh,
          const float* __restrict__ W_fc, const float* __restrict__ b_fc,
          float* __restrict__ out)
{
    extern __shared__ float sm[];
    const int tid = threadIdx.x;
    const int bid = blockIdx.x;

    // ---- init state to zero ----
    {
        float* h0 = &g_hbuf[0][0][0][0][0];
        for (int e = bid * NT + tid; e < 2 * 2 * BATCH * LHID; e += NB * NT) h0[e] = 0.0f;
        float* c0 = &g_c[0][0][0][0];
        for (int e = bid * NT + tid; e < 2 * 2 * BATCH * LHID; e += NB * NT) c0[e] = 0.0f;
        float* p0 = &g_prev[0][0];
        for (int e = bid * NT + tid; e < BATCH * OUT_SZ; e += NB * NT) p0[e] = 0.0f;
    }

    // block mapping: 128 blocks = 2 dirs x 64 unit-groups of 8 units
    const int d     = bid >> 6;
    const int u0    = (bid & 63) << 3;
    const int grp   = tid >> 5;        // k-group == warp (0..15)
    const int t32   = tid & 31;
    const int trow4 = t32 >> 3;        // 0..3: rows trow4*8 .. +7
    const int tcol  = t32 & 7;         // 0..7: cols tcol, +8, +16, +24

    float* red   = sm + 2 * BUFSZ;         // 16896 floats (x-buf region)
    float* hs    = sm;                     // FC: 32*1028 = 32896
    float* wfc_s = sm + 32 * 1028;         // FC: 4096
    float* fcred = wfc_s + 4096;           // FC: 512

    const float* wih0 = W_ih + (size_t)(0 * 2 + d) * 2048 * 1024;
    const float* whh0 = W_hh + (size_t)(0 * 2 + d) * 2048 * 512;
    const float* wih1 = W_ih + (size_t)(1 * 2 + d) * 2048 * 1024;
    const float* whh1 = W_hh + (size_t)(1 * 2 + d) * 2048 * 512;

    // stage weights of layer l, chunk ch into w-buffer b (warp-private slice).
    // XOR slot swizzle: slot = (kq4 + (r>>3)) & 3 -> conflict-free wv broadcast loads.
    auto stage_w = [&](int l, int ch, int b) {
        const int k0 = grp * KPG + ch * KC;
        const float* base; int stride;
        if (k0 < 1024) { base = (l ? wih1 : wih0) + k0;          stride = 1024; }
        else           { base = (l ? whh1 : whh0) + (k0 - 1024); stride = 512;  }
        float* wbuf = sm + b * BUFSZ + grp * SLICE;
        #pragma unroll
        for (int p = 0; p < 4; ++p) {
            int idx = p * 32 + t32;
            int r = idx >> 2, kq4 = idx & 3;
            int grow = ((r >> 3) << 9) + u0 + (r & 7);
            int slot = (kq4 + (r >> 3)) & 3;
            cp_async16(&wbuf[r * PADK + slot * 4], base + (size_t)grow * stride + kq4 * 4);
        }
    };

    // stage activations of layer l, chunk ch (uniform base+stride per chunk)
    auto stage_x = [&](int l, int ch, int b, int t, int rp, int wp) {
        const int k0 = grp * KPG + ch * KC;
        const float* bx; int sx;
        if (l == 0) {
            if (k0 < 512)       { bx = x_in + (size_t)t * IN_SZ + k0;        sx = T_STEPS * IN_SZ; }
            else if (k0 < 1024) { bx = &g_prev[0][k0 - 512];                 sx = OUT_SZ; }
            else                { bx = &g_hbuf[rp][0][d][0][k0 - 1024];      sx = LHID; }
        } else {
            if (k0 < 512)       { bx = &g_hbuf[wp][0][0][0][k0];             sx = LHID; }
            else if (k0 < 1024) { bx = &g_hbuf[wp][0][1][0][k0 - 512];       sx = LHID; }
            else                { bx = &g_hbuf[rp][1][d][0][k0 - 1024];      sx = LHID; }
        }
        float* xbuf = sm + (2 + b) * BUFSZ + grp * SLICE;
        #pragma unroll
        for (int p = 0; p < 4; ++p) {
            int idx = p * 32 + t32;
            int c = idx >> 2, kq4 = idx & 3;
            cp_async16(&xbuf[c * PADK + kq4 * 4], bx + (size_t)c * sx + kq4 * 4);
        }
    };

    // prologue: pre-issue weights for (t=0, l=0) chunks 0,1; then global init sync
    stage_w(0, 0, 0);
    stage_w(0, 1, 1);
    grid_sync();

    for (int t = 0; t < T_STEPS; ++t) {
        const int rp = t & 1;
        const int wp = rp ^ 1;

        for (int l = 0; l < 2; ++l) {
            // entry invariant: w(ch0)->wbuf0, w(ch1)->wbuf1 already issued (uncommitted)
            stage_x(l, 0, 0, t, rp, wp); cp_commit();   // G0 = {w0, w1, x0}
            stage_x(l, 1, 1, t, rp, wp); cp_commit();   // G1 = {x1}

            float acc[8][4];
            #pragma unroll
            for (int i = 0; i < 8; ++i)
                #pragma unroll
                for (int j = 0; j < 4; ++j) acc[i][j] = 0.0f;

            #pragma unroll
            for (int ch = 0; ch < NCH; ++ch) {
                if (ch < NCH - 1) cp_wait<1>(); else cp_wait<0>();
                // warp-private buffers: NO block barrier in this loop
                const float* wb = sm + (ch & 1) * BUFSZ + grp * SLICE;
                const float* xb = sm + (2 + (ch & 1)) * BUFSZ + grp * SLICE;
                #pragma unroll
                for (int kq = 0; kq < 4; ++kq) {
                    float4 xv[4];
                    #pragma unroll
                    for (int j = 0; j < 4; ++j)
                        xv[j] = *(const float4*)&xb[(tcol + 8 * j) * PADK + kq * 4];
                    const int wslot = ((kq + trow4) & 3) * 4;
                    #pragma unroll
                    for (int i = 0; i < 8; ++i) {
                        float4 wv = *(const float4*)&wb[(trow4 * 8 + i) * PADK + wslot];
                        #pragma unroll
                        for (int j = 0; j < 4; ++j) {
                            acc[i][j] += wv.x * xv[j].x;
                            acc[i][j] += wv.y * xv[j].y;
                            acc[i][j] += wv.z * xv[j].z;
                            acc[i][j] += wv.w * xv[j].w;
                        }
                    }
                }
                if (ch < NCH - 2) {        // refill the buffer just consumed
                    stage_w(l, ch + 2, ch & 1);
                    stage_x(l, ch + 2, ch & 1, t, rp, wp);
                    cp_commit();
                }
            }

            __syncthreads();   // red overlays x-bufs (cross-warp) — all computes done
            #pragma unroll
            for (int i = 0; i < 8; ++i)
                #pragma unroll
                for (int j = 0; j < 4; ++j)
                    red[(grp * 32 + trow4 * 8 + i) * 33 + (tcol + 8 * j)] = acc[i][j];
            __syncthreads();

            // cell: direct 16-partial sum + bias; 256 active thr = 32 batch x 8 units
            if (tid < 256) {
                int c = tid >> 3, j = tid & 7;
                float g4[4];
                #pragma unroll
                for (int gate = 0; gate < 4; ++gate) {
                    int r = gate * 8 + j;
                    float s = 0.0f;
                    #pragma unroll
                    for (int g = 0; g < NG; ++g)
                        s += red[(g * 32 + r) * 33 + c];
                    int bo = (l * 2 + d) * 2048 + (gate << 9) + u0 + j;
                    g4[gate] = s + b_ih[bo] + b_hh[bo];
                }
                float cold = g_c[l][d][c][u0 + j];
                float cn = sigm(g4[1]) * cold + sigm(g4[0]) * tanhf(g4[2]);
                float hn = sigm(g4[3]) * tanhf(cn);
                g_c[l][d][c][u0 + j] = cn;
                g_hbuf[wp][l][d][c][u0 + j] = hn;
            }

            // pre-issue next phase's independent loads before the barrier.
            // l==1: wfc_s overlays red's tail -> MUST retire all red reads first
            // (this missing barrier was the R10 correctness bug).
            if (l == 1) __syncthreads();
            if (l == 0) {
                stage_w(1, 0, 0);
                stage_w(1, 1, 1);
            } else {
                #pragma unroll
                for (int p = 0; p < 2; ++p) {
                    int i2 = p * NT + tid;     // 1024 float4
                    cp_async16(&wfc_s[i2 * 4], W_fc + ((size_t)(bid << 2)) * 1024 + i2 * 4);
                }
            }
            grid_sync();
        }

        // ---- FC phase: pred = h1cat @ W_fc^T + b_fc ----
        {
            #pragma unroll
            for (int p = 0; p < 16; ++p) {
                int idx = p * NT + tid;        // 8192 float4
                int c = idx >> 8, kq = idx & 255;
                int k = kq * 4;
                const float* src = (k < 512) ? &g_hbuf[wp][1][0][c][k]
                                             : &g_hbuf[wp][1][1][c][k - 512];
                cp_async16(&hs[c * 1028 + k], src);
            }
            cp_commit();                       // bundles the prestaged wfc too
            cp_wait<0>();
            __syncthreads();

            const int o0 = bid << 2;
            const int kh = tid >> 7, t2 = tid & 127;   // kh: 0..3 k-quarters of 256
            const int ol = t2 >> 5, c = t2 & 31;
            float a = 0.0f;
            const float* wrow = wfc_s + ol * 1024 + kh * 256;
            const float* xrow = hs + c * 1028 + kh * 256;
            #pragma unroll 8
            for (int q = 0; q < 64; ++q) {
                float4 wv = *(const float4*)(wrow + q * 4);
                float4 xv = *(const float4*)(xrow + q * 4);
                a += wv.x * xv.x; a += wv.y * xv.y;
                a += wv.z * xv.z; a += wv.w * xv.w;
            }
            fcred[kh * 128 + t2] = a;
            __syncthreads();

            // pre-issue next step's layer-0 weights (hs/w-buf reads all retired
            // at the barrier above; fcred does not overlap the w-buffers)
            if (t + 1 < T_STEPS) {
                stage_w(0, 0, 0);
                stage_w(0, 1, 1);
            }
            if (tid < 128) {
                int c2 = tid >> 2, oo = tid & 3;
                int idx = oo * 32 + c2;
                float v = fcred[idx] + fcred[128 + idx] + fcred[256 + idx] + fcred[384 + idx]
                        + b_fc[o0 + oo];
                out[((size_t)c2 * T_STEPS + t) * OUT_SZ + o0 + oo] = v;
                g_prev[c2][o0 + oo] = v;
            }
            grid_sync();
        }
    }

    // ---- final h_n, c_n (last write parity = T&1 = 0); __ldcg for cross-SM data ----
    {
        const float* hsrc = &g_hbuf[0][0][0][0][0];
        const float* csrc = &g_c[0][0][0][0];
        for (int e = bid * NT + tid; e < 2 * 2 * BATCH * LHID; e += NB * NT) {
            out[HN_BASE + e] = __ldcg(&hsrc[e]);
            out[HN_BASE + 65536 + e] = __ldcg(&csrc[e]);
        }
    }
}

extern "C" void kernel_launch(void* const* d_in, const int* in_sizes, int n_in,
                              void* d_out, int out_size) {
    const float* input_seq = (const float*)d_in[0];
    // d_in[1] = input_lengths (all == T, unused by the reference path)
    const float* W_ih = (const float*)d_in[2];
    const float* W_hh = (const float*)d_in[3];
    const float* b_ih = (const float*)d_in[4];
    const float* b_hh = (const float*)d_in[5];
    const float* W_fc = (const float*)d_in[6];
    const float* b_fc = (const float*)d_in[7];
    float* out = (float*)d_out;

    cudaFuncSetAttribute(ae_kernel, cudaFuncAttributeMaxDynamicSharedMemorySize, SMEM_BYTES);
    ae_kernel<<<NB, NT, SMEM_BYTES>>>(input_seq, W_ih, W_hh, b_ih, b_hh, W_fc, b_fc, out);
}

// round 12
// speedup vs baseline: 1.1147x; 1.1147x over previous
#include <cuda_runtime.h>
#include <math.h>

// Problem constants
#define NB        128      // persistent blocks (<= 148 SMs, all resident)
#define NT        256      // 8 warps = 8 warp-private k-groups
#define T_STEPS   512
#define BATCH     32
#define IN_SZ     512
#define OUT_SZ    512
#define LHID      512
#define NG        8        // k-groups (one warp each)
#define KPG       192      // K per group (1536/8)
#define KC        32       // k per chunk per group
#define NCH       6        // chunks (192/32)
#define PADK      36       // row stride 144B
#define SLICE     (32 * PADK)                  // 1152 floats per-warp slice
#define BUFSZ     (NG * SLICE)                 // 9216 floats per buffer
#define HN_BASE   (BATCH * T_STEPS * OUT_SZ)   // 8,388,608
#define TOTAL_SYNCS 1537u                      // 1 + 3*T_STEPS

// Persistent state (device globals; no allocation allowed)
__device__ float g_hbuf[2][2][2][BATCH][LHID];  // [parity][layer][dir][b][u]
__device__ float g_c[2][2][BATCH][LHID];        // [layer][dir][b][u]
__device__ float g_prev[BATCH][OUT_SZ];
// multi-flag barrier state: one cacheline-spaced flag per block, monotonic gens
__device__ volatile unsigned g_flag[NB * 32];
__device__ unsigned g_base = 0;

// Parallel-arrival grid barrier: per-block flag store + per-thread flag poll.
// No atomics -> no LTS serialization chain. gens are globally monotonic
// (g_base carried across launches), so stale flags never satisfy a new wait.
__device__ __forceinline__ void grid_sync(unsigned gen) {
    __threadfence();
    __syncthreads();
    if (threadIdx.x == 0) g_flag[blockIdx.x * 32] = gen;
    if (threadIdx.x < NB) {
        while (g_flag[threadIdx.x * 32] < gen) { }
    }
    __threadfence();
    __syncthreads();
}

__device__ __forceinline__ float sigm(float x) { return 1.0f / (1.0f + expf(-x)); }

// cp.async (L2-only .cg path: coherent with other SMs' writes, no L1 staleness)
__device__ __forceinline__ void cp_async16(void* smem_dst, const void* gsrc) {
    unsigned saddr = (unsigned)__cvta_generic_to_shared(smem_dst);
    asm volatile("cp.async.cg.shared.global [%0], [%1], 16;\n" :: "r"(saddr), "l"(gsrc));
}
__device__ __forceinline__ void cp_commit() {
    asm volatile("cp.async.commit_group;\n");
}
template <int N> __device__ __forceinline__ void cp_wait() {
    asm volatile("cp.async.wait_group %0;\n" :: "n"(N));
}

// smem (floats):
//   wbuf0 [0,9216) | wbuf1 [9216,18432) | xbuf0 [18432,27648) | xbuf1 [27648,36864)
//   red   [36864,45312)  DEDICATED (no overlay hazards)
//   wfc   [45312,49408)  DEDICATED, staged once in prologue (W_fc is constant)
//   fcred [49408,49664)
//   FC overlay: hs [0,32896) over the four buffers (reads retired before reuse)
#define SMEM_FLOATS 49664
#define SMEM_BYTES  (SMEM_FLOATS * 4)

__global__ void __launch_bounds__(NT, 1)
ae_kernel(const float* __restrict__ x_in,
          const float* __restrict__ W_ih, const float* __restrict__ W_hh,
          const float* __restrict__ b_ih, const float* __restrict__ b_hh,
          const float* __restrict__ W_fc, const float* __restrict__ b_fc,
          float* __restrict__ out)
{
    extern __shared__ float sm[];
    const int tid = threadIdx.x;
    const int bid = blockIdx.x;
    const unsigned base = g_base;          // uniform across the launch

    // ---- init state to zero ----
    {
        float* h0 = &g_hbuf[0][0][0][0][0];
        for (int e = bid * NT + tid; e < 2 * 2 * BATCH * LHID; e += NB * NT) h0[e] = 0.0f;
        float* c0 = &g_c[0][0][0][0];
        for (int e = bid * NT + tid; e < 2 * 2 * BATCH * LHID; e += NB * NT) c0[e] = 0.0f;
        float* p0 = &g_prev[0][0];
        for (int e = bid * NT + tid; e < BATCH * OUT_SZ; e += NB * NT) p0[e] = 0.0f;
    }

    // block mapping: 128 blocks = 2 dirs x 64 unit-groups of 8 units
    const int d     = bid >> 6;
    const int u0    = (bid & 63) << 3;
    const int grp   = tid >> 5;        // k-group == warp
    const int t32   = tid & 31;
    const int trow4 = t32 >> 3;        // 0..3: rows trow4*8 .. +7
    const int tcol  = t32 & 7;         // 0..7: cols tcol, +8, +16, +24

    float* red   = sm + 4 * BUFSZ;         // dedicated, 8448 floats
    float* wfc_s = red + NG * 32 * 33;     // dedicated, 4096 floats
    float* fcred = wfc_s + 4096;           // 256 floats
    float* hs    = sm;                     // FC overlay: 32*1028 = 32896

    const float* wih0 = W_ih + (size_t)(0 * 2 + d) * 2048 * 1024;
    const float* whh0 = W_hh + (size_t)(0 * 2 + d) * 2048 * 512;
    const float* wih1 = W_ih + (size_t)(1 * 2 + d) * 2048 * 1024;
    const float* whh1 = W_hh + (size_t)(1 * 2 + d) * 2048 * 512;

    // stage weights of layer l, chunk ch into w-buffer b (warp-private slice).
    // XOR slot swizzle: slot = (kq4 + (r>>3)) & 7 -> conflict-free wv LDS.
    auto stage_w = [&](int l, int ch, int b) {
        const int k0 = grp * KPG + ch * KC;
        const float* base_; int stride;
        if (k0 < 1024) { base_ = (l ? wih1 : wih0) + k0;          stride = 1024; }
        else           { base_ = (l ? whh1 : whh0) + (k0 - 1024); stride = 512;  }
        float* wbuf = sm + b * BUFSZ + grp * SLICE;
        #pragma unroll
        for (int p = 0; p < 8; ++p) {
            int idx = p * 32 + t32;
            int r = idx >> 3, kq4 = idx & 7;
            int grow = ((r >> 3) << 9) + u0 + (r & 7);
            int slot = (kq4 + (r >> 3)) & 7;
            cp_async16(&wbuf[r * PADK + slot * 4], base_ + (size_t)grow * stride + kq4 * 4);
        }
    };

    // stage activations of layer l, chunk ch (uniform base+stride per chunk)
    auto stage_x = [&](int l, int ch, int b, int t, int rp, int wp) {
        const int k0 = grp * KPG + ch * KC;
        const float* bx; int sx;
        if (l == 0) {
            if (k0 < 512)       { bx = x_in + (size_t)t * IN_SZ + k0;        sx = T_STEPS * IN_SZ; }
            else if (k0 < 1024) { bx = &g_prev[0][k0 - 512];                 sx = OUT_SZ; }
            else                { bx = &g_hbuf[rp][0][d][0][k0 - 1024];      sx = LHID; }
        } else {
            if (k0 < 512)       { bx = &g_hbuf[wp][0][0][0][k0];             sx = LHID; }
            else if (k0 < 1024) { bx = &g_hbuf[wp][0][1][0][k0 - 512];       sx = LHID; }
            else                { bx = &g_hbuf[rp][1][d][0][k0 - 1024];      sx = LHID; }
        }
        float* xbuf = sm + (2 + b) * BUFSZ + grp * SLICE;
        #pragma unroll
        for (int p = 0; p < 8; ++p) {
            int idx = p * 32 + t32;
            int c = idx >> 3, kq4 = idx & 7;
            cp_async16(&xbuf[c * PADK + kq4 * 4], bx + (size_t)c * sx + kq4 * 4);
        }
    };

    // warps 0..2: layer-0 chunks 0/1 read only static x_in -> prestagable
    const bool pre_x0 = (grp < 3);

    // ---- prologue ----
    // wfc (constant) staged ONCE; then weights for (t=0,l=0) chunks 0,1;
    // x prestage for warps 0..2 (commits form G0={wfc,w0,w1,x0}, G1={x1}).
    #pragma unroll
    for (int p = 0; p < 4; ++p) {
        int i2 = p * NT + tid;     // 1024 float4
        cp_async16(&wfc_s[i2 * 4], W_fc + ((size_t)(bid << 2)) * 1024 + i2 * 4);
    }
    stage_w(0, 0, 0);
    stage_w(0, 1, 1);
    if (pre_x0) {
        stage_x(0, 0, 0, 0, 0, 1); cp_commit();
        stage_x(0, 1, 1, 0, 0, 1); cp_commit();
    }
    grid_sync(base + 1);

    unsigned gen = base + 1;

    for (int t = 0; t < T_STEPS; ++t) {
        const int rp = t & 1;
        const int wp = rp ^ 1;

        for (int l = 0; l < 2; ++l) {
            // entry: G0={w0,w1,x0}, G1={x1}; for (l==0, grp<3) already committed
            if (!(l == 0 && pre_x0)) {
                stage_x(l, 0, 0, t, rp, wp); cp_commit();
                stage_x(l, 1, 1, t, rp, wp); cp_commit();
            }

            float acc[8][4];
            #pragma unroll
            for (int i = 0; i < 8; ++i)
                #pragma unroll
                for (int j = 0; j < 4; ++j) acc[i][j] = 0.0f;

            #pragma unroll
            for (int ch = 0; ch < NCH; ++ch) {
                if (ch < NCH - 1) cp_wait<1>(); else cp_wait<0>();
                // warp-private buffers: NO block barrier in this loop
                const float* wb = sm + (ch & 1) * BUFSZ + grp * SLICE;
                const float* xb = sm + (2 + (ch & 1)) * BUFSZ + grp * SLICE;
                #pragma unroll
                for (int kq = 0; kq < 8; ++kq) {
                    float4 xv[4];
                    #pragma unroll
                    for (int j = 0; j < 4; ++j)
                        xv[j] = *(const float4*)&xb[(tcol + 8 * j) * PADK + kq * 4];
                    const int wslot = ((kq + trow4) & 7) * 4;
                    #pragma unroll
                    for (int i = 0; i < 8; ++i) {
                        float4 wv = *(const float4*)&wb[(trow4 * 8 + i) * PADK + wslot];
                        #pragma unroll
                        for (int j = 0; j < 4; ++j) {
                            acc[i][j] += wv.x * xv[j].x;
                            acc[i][j] += wv.y * xv[j].y;
                            acc[i][j] += wv.z * xv[j].z;
                            acc[i][j] += wv.w * xv[j].w;
                        }
                    }
                }
                if (ch < NCH - 2) {        // refill the buffer just consumed
                    stage_w(l, ch + 2, ch & 1);
                    stage_x(l, ch + 2, ch & 1, t, rp, wp);
                    cp_commit();
                }
            }

            // red is DEDICATED: write partials directly (warp-private rows)
            #pragma unroll
            for (int i = 0; i < 8; ++i)
                #pragma unroll
                for (int j = 0; j < 4; ++j)
                    red[(grp * 32 + trow4 * 8 + i) * 33 + (tcol + 8 * j)] = acc[i][j];
            __syncthreads();

            // cell: direct 8-partial sum + bias; 256 thr = 32 batch x 8 units
            {
                int c = tid >> 3, j = tid & 7;
                float g4[4];
                #pragma unroll
                for (int gate = 0; gate < 4; ++gate) {
                    int r = gate * 8 + j;
                    float s = 0.0f;
                    #pragma unroll
                    for (int g = 0; g < NG; ++g)
                        s += red[(g * 32 + r) * 33 + c];
                    int bo = (l * 2 + d) * 2048 + (gate << 9) + u0 + j;
                    g4[gate] = s + b_ih[bo] + b_hh[bo];
                }
                float cold = g_c[l][d][c][u0 + j];
                float cn = sigm(g4[1]) * cold + sigm(g4[0]) * tanhf(g4[2]);
                float hn = sigm(g4[3]) * tanhf(cn);
                g_c[l][d][c][u0 + j] = cn;
                g_hbuf[wp][l][d][c][u0 + j] = hn;
            }

            // pre-issue next layer's weights before the barrier (hidden by sync)
            if (l == 0) {
                stage_w(1, 0, 0);
                stage_w(1, 1, 1);
            }
            grid_sync(++gen);
        }

        // ---- FC phase: pred = h1cat @ W_fc^T + b_fc (wfc_s resident) ----
        {
            #pragma unroll 8
            for (int p = 0; p < 32; ++p) {
                int idx = p * NT + tid;        // 8192 float4
                int c = idx >> 8, kq = idx & 255;
                int k = kq * 4;
                const float* src = (k < 512) ? &g_hbuf[wp][1][0][c][k]
                                             : &g_hbuf[wp][1][1][c][k - 512];
                cp_async16(&hs[c * 1028 + k], src);
            }
            cp_commit();
            cp_wait<0>();
            __syncthreads();

            const int o0 = bid << 2;
            const int kh = tid >> 7, t2 = tid & 127;
            const int ol = t2 >> 5, c = t2 & 31;
            float a = 0.0f;
            const float* wrow = wfc_s + ol * 1024 + kh * 512;
            const float* xrow = hs + c * 1028 + kh * 512;
            #pragma unroll 8
            for (int q = 0; q < 128; ++q) {
                float4 wv = *(const float4*)(wrow + q * 4);
                float4 xv = *(const float4*)(xrow + q * 4);
                a += wv.x * xv.x; a += wv.y * xv.y;
                a += wv.z * xv.z; a += wv.w * xv.w;
            }
            fcred[kh * 128 + t2] = a;
            __syncthreads();           // retires hs reads -> buffers reusable

            // pre-issue next step's layer-0 weights + (warps 0-2) x_in chunks
            if (t + 1 < T_STEPS) {
                stage_w(0, 0, 0);
                stage_w(0, 1, 1);
                if (pre_x0) {
                    stage_x(0, 0, 0, t + 1, 0, 0); cp_commit();
                    stage_x(0, 1, 1, t + 1, 0, 0); cp_commit();
                }
            }
            if (tid < 128) {
                int c2 = tid >> 2, oo = tid & 3;
                int idx = oo * 32 + c2;
                float v = fcred[idx] + fcred[128 + idx] + b_fc[o0 + oo];
                out[((size_t)c2 * T_STEPS + t) * OUT_SZ + o0 + oo] = v;
                g_prev[c2][o0 + oo] = v;
            }
            grid_sync(++gen);
        }
    }

    // ---- final h_n, c_n (last write parity = T&1 = 0); __ldcg for cross-SM data ----
    {
        const float* hsrc = &g_hbuf[0][0][0][0][0];
        const float* csrc = &g_c[0][0][0][0];
        for (int e = bid * NT + tid; e < 2 * 2 * BATCH * LHID; e += NB * NT) {
            out[HN_BASE + e] = __ldcg(&hsrc[e]);
            out[HN_BASE + 65536 + e] = __ldcg(&csrc[e]);
        }
    }

    // advance persistent barrier generation base for the next launch
    if (bid == 0 && tid == 0) g_base = base + TOTAL_SYNCS;
}

extern "C" void kernel_launch(void* const* d_in, const int* in_sizes, int n_in,
                              void* d_out, int out_size) {
    const float* input_seq = (const float*)d_in[0];
    // d_in[1] = input_lengths (all == T, unused by the reference path)
    const float* W_ih = (const float*)d_in[2];
    const float* W_hh = (const float*)d_in[3];
    const float* b_ih = (const float*)d_in[4];
    const float* b_hh = (const float*)d_in[5];
    const float* W_fc = (const float*)d_in[6];
    const float* b_fc = (const float*)d_in[7];
    float* out = (float*)d_out;

    cudaFuncSetAttribute(ae_kernel, cudaFuncAttributeMaxDynamicSharedMemorySize, SMEM_BYTES);
    ae_kernel<<<NB, NT, SMEM_BYTES>>>(input_seq, W_ih, W_hh, b_ih, b_hh, W_fc, b_fc, out);
}